// round 7
// baseline (speedup 1.0000x reference)
#include <cuda_runtime.h>

#define NUM_LEVELS 256

__device__ __forceinline__ float quantize_one(float v) {
    // Nearest center of linspace(-1, 1, 256): i = round((v+1)*127.5), clamp [0,255].
    // Round-to-nearest-even via magic-number add/sub (stays on 4-cyc FMA pipe,
    // avoids the ~20-cyc cvt/FRND pipe). t is in [~-inf, +inf] but clamped first
    // so |t| < 2^22 holds for the magic trick.
    float t = fmaf(v, 127.5f, 127.5f);
    t = fmaxf(0.0f, fminf(255.0f, t));          // clamp before round (monotone => equivalent)
    const float MAGIC = 12582912.0f;            // 1.5 * 2^23
    float r = (t + MAGIC) - MAGIC;              // rint(t) for 0 <= t <= 255
    // Reconstruct center: -1 + r * (2/255)
    return fmaf(r, 2.0f / 255.0f, -1.0f);
}

__device__ __forceinline__ float4 quantize_vec(float4 v) {
    float4 o;
    o.x = quantize_one(v.x);
    o.y = quantize_one(v.y);
    o.z = quantize_one(v.z);
    o.w = quantize_one(v.w);
    return o;
}

#define UNROLL 2

__global__ void __launch_bounds__(256) nq_kernel(
    const float4* __restrict__ x4,
    float4* __restrict__ out4,
    int n4)
{
    int base = blockIdx.x * (blockDim.x * UNROLL) + threadIdx.x;
    const int s = blockDim.x;

    if (base + (UNROLL - 1) * s < n4) {
        // Two independent loads issued back-to-back (L2-hot in the replay loop).
        float4 v0 = x4[base + 0 * s];
        float4 v1 = x4[base + 1 * s];
        out4[base + 0 * s] = quantize_vec(v0);
        out4[base + 1 * s] = quantize_vec(v1);
    } else {
        #pragma unroll
        for (int u = 0; u < UNROLL; u++) {
            int idx = base + u * s;
            if (idx < n4) out4[idx] = quantize_vec(x4[idx]);
        }
    }
}

__global__ void __launch_bounds__(256) nq_tail_kernel(
    const float* __restrict__ x,
    float* __restrict__ out,
    int start, int n)
{
    int i = start + blockIdx.x * blockDim.x + threadIdx.x;
    if (i < n) out[i] = quantize_one(x[i]);
}

extern "C" void kernel_launch(void* const* d_in, const int* in_sizes, int n_in,
                              void* d_out, int out_size) {
    const float* x = (const float*)d_in[0];
    float* out = (float*)d_out;
    int n = in_sizes[0];

    int n4 = n / 4;
    if (n4 > 0) {
        const int threads = 256;
        int per_block = threads * UNROLL;
        int blocks = (n4 + per_block - 1) / per_block;
        nq_kernel<<<blocks, threads>>>((const float4*)x, (float4*)out, n4);
    }
    int tail_start = n4 * 4;
    int tail = n - tail_start;
    if (tail > 0) {
        nq_tail_kernel<<<1, 256>>>(x, out, tail_start, n);
    }
}

// round 11
// speedup vs baseline: 1.0386x; 1.0386x over previous
#include <cuda_runtime.h>

#define NUM_LEVELS 256

__device__ __forceinline__ float quantize_one(float v) {
    // Nearest center of linspace(-1, 1, 256): i = round((v+1)*127.5), clamp [0,255].
    // Round-to-nearest-even via magic-number add/sub (4-cyc FMA pipe, no cvt pipe).
    float t = fmaf(v, 127.5f, 127.5f);
    t = fmaxf(0.0f, fminf(255.0f, t));
    const float MAGIC = 12582912.0f;            // 1.5 * 2^23
    float r = (t + MAGIC) - MAGIC;              // rint(t) for 0 <= t <= 255
    return fmaf(r, 2.0f / 255.0f, -1.0f);       // center = -1 + i * (2/255)
}

// 256-bit global load/store (sm_100+: LDG.E.256 / STG.E.256).
__device__ __forceinline__ void ldg_v8(const float* __restrict__ p, float r[8]) {
    asm volatile("ld.global.v8.f32 {%0,%1,%2,%3,%4,%5,%6,%7}, [%8];"
                 : "=f"(r[0]), "=f"(r[1]), "=f"(r[2]), "=f"(r[3]),
                   "=f"(r[4]), "=f"(r[5]), "=f"(r[6]), "=f"(r[7])
                 : "l"(p));
}
__device__ __forceinline__ void stg_v8(float* __restrict__ p, const float r[8]) {
    asm volatile("st.global.v8.f32 [%0], {%1,%2,%3,%4,%5,%6,%7,%8};"
                 :: "l"(p),
                    "f"(r[0]), "f"(r[1]), "f"(r[2]), "f"(r[3]),
                    "f"(r[4]), "f"(r[5]), "f"(r[6]), "f"(r[7])
                 : "memory");
}

__global__ void __launch_bounds__(256) nq_kernel_v8(
    const float* __restrict__ x,
    float* __restrict__ out,
    int n8)   // number of float8 chunks
{
    int idx = blockIdx.x * blockDim.x + threadIdx.x;
    if (idx < n8) {
        float r[8];
        ldg_v8(x + (size_t)idx * 8, r);
        #pragma unroll
        for (int k = 0; k < 8; k++) r[k] = quantize_one(r[k]);
        stg_v8(out + (size_t)idx * 8, r);
    }
}

__global__ void __launch_bounds__(256) nq_tail_kernel(
    const float* __restrict__ x,
    float* __restrict__ out,
    int start, int n)
{
    int i = start + blockIdx.x * blockDim.x + threadIdx.x;
    if (i < n) out[i] = quantize_one(x[i]);
}

extern "C" void kernel_launch(void* const* d_in, const int* in_sizes, int n_in,
                              void* d_out, int out_size) {
    const float* x = (const float*)d_in[0];
    float* out = (float*)d_out;
    int n = in_sizes[0];

    int n8 = n / 8;
    if (n8 > 0) {
        const int threads = 256;
        int blocks = (n8 + threads - 1) / threads;
        nq_kernel_v8<<<blocks, threads>>>(x, out, n8);
    }
    int tail_start = n8 * 8;
    int tail = n - tail_start;
    if (tail > 0) {
        nq_tail_kernel<<<1, 256>>>(x, out, tail_start, n);
    }
}